// round 1
// baseline (speedup 1.0000x reference)
#include <cuda_runtime.h>

#define XD 38
#define YD 24
#define ZD 24
#define RV (XD*YD*ZD)      // 21888 voxels
#define BB 16
#define CC 64
#define NN 16384

// scratch (no allocations allowed -> __device__ globals)
__device__ int   g_flat[BB*NN];   // voxel id per point, -1 if invalid
__device__ float g_inv [BB*NN];   // 1/count of that point's voxel
__device__ int   g_cnt [BB*RV];   // per-voxel point count

static const int OUT_FLOATS = BB*CC*RV;       // 22,413,312
static const int OUT_VEC4   = OUT_FLOATS/4;   // 5,603,328
static const int CNT_VEC4   = (BB*RV)/4;      // 87,552

__global__ void zero_k(float4* __restrict__ out) {
    int i = blockIdx.x * blockDim.x + threadIdx.x;
    if (i < OUT_VEC4) out[i] = make_float4(0.f, 0.f, 0.f, 0.f);
    if (i < CNT_VEC4) reinterpret_cast<int4*>(g_cnt)[i] = make_int4(0,0,0,0);
}

__global__ void index_k(const float* __restrict__ coords) {
    int i = blockIdx.x * blockDim.x + threadIdx.x;   // point id in [0, B*N)
    if (i >= BB*NN) return;
    float cx = coords[3*i + 0];
    float cy = coords[3*i + 1];
    float cz = coords[3*i + 2];
    // idx = floor(coord / voxel_size) - min_voxel_coord ; mvc = [-19,-12,-12]
    int ix = (int)floorf(cx / 0.3f) + 19;
    int iy = (int)floorf(cy / 0.3f) + 12;
    int iz = (int)floorf(cz / 0.2f) + 12;
    bool valid = (ix >= 0) & (ix < XD) & (iy >= 0) & (iy < YD) & (iz >= 0) & (iz < ZD);
    int flat = -1;
    if (valid) {
        flat = ix * (YD*ZD) + iy * ZD + iz;
        int b = i / NN;
        atomicAdd(&g_cnt[b*RV + flat], 1);
    }
    g_flat[i] = flat;
}

__global__ void inv_k() {
    int i = blockIdx.x * blockDim.x + threadIdx.x;
    if (i >= BB*NN) return;
    int flat = g_flat[i];
    float inv = 0.f;
    if (flat >= 0) {
        int b = i / NN;
        int c = g_cnt[b*RV + flat];     // >= 1 since this point counted itself
        inv = 1.0f / (float)c;
    }
    g_inv[i] = inv;
}

// grid: (N/1024, C, B), 256 threads, 4 points per thread (vectorized)
__global__ void scatter_k(const float* __restrict__ feat, float* __restrict__ out) {
    int b = blockIdx.z;
    int c = blockIdx.y;
    int p0 = (blockIdx.x * blockDim.x + threadIdx.x) * 4;

    const float4 f  = *reinterpret_cast<const float4*>(feat + ((size_t)(b*CC + c)*NN + p0));
    const int4   fl = *reinterpret_cast<const int4*>  (g_flat + b*NN + p0);
    const float4 iv = *reinterpret_cast<const float4*>(g_inv  + b*NN + p0);

    float* ob = out + (size_t)(b*CC + c)*RV;
    if (fl.x >= 0) atomicAdd(ob + fl.x, f.x * iv.x);
    if (fl.y >= 0) atomicAdd(ob + fl.y, f.y * iv.y);
    if (fl.z >= 0) atomicAdd(ob + fl.z, f.z * iv.z);
    if (fl.w >= 0) atomicAdd(ob + fl.w, f.w * iv.w);
}

extern "C" void kernel_launch(void* const* d_in, const int* in_sizes, int n_in,
                              void* d_out, int out_size) {
    const float* feat   = (const float*)d_in[0];   // [B, C, N]
    const float* coords = (const float*)d_in[1];   // [B, N, 3]
    float* out = (float*)d_out;                    // [B, C, X, Y, Z]

    // 1) zero output + counts
    {
        int threads = 256;
        int blocks = (OUT_VEC4 + threads - 1) / threads;   // 21888
        zero_k<<<blocks, threads>>>(reinterpret_cast<float4*>(out));
    }
    // 2) per-point voxel index + counts
    {
        int threads = 256;
        int blocks = (BB*NN + threads - 1) / threads;      // 1024
        index_k<<<blocks, threads>>>(coords);
    }
    // 3) per-point 1/count
    {
        int threads = 256;
        int blocks = (BB*NN + threads - 1) / threads;
        inv_k<<<blocks, threads>>>();
    }
    // 4) scatter-mean features into output
    {
        dim3 grid(NN / (256*4), CC, BB);                   // (16, 64, 16)
        scatter_k<<<grid, 256>>>(feat, out);
    }
}